// round 15
// baseline (speedup 1.0000x reference)
#include <cuda_runtime.h>
#include <cuda_fp16.h>
#include <cuda_bf16.h>
#include <cstdint>

// NPSCalculator: nps = sum_{b,h,w} min_k sqrt( sum_c (x[b,c,h,w] - p[k,c] + 1e-6)^2 + 1e-6 ) / size
// B=8, C=3, H=512, W=512, NUM_COLORS=30.
//
// R15: pair-granularity argmin. All structural experiments (occupancy, prefetch, reload)
// were flat -> the kernel sits near its issue-count floor; cut instructions.
// 30 colors = 15 pairs: per pixel-pair per color-pair: 6 hfma.f16x2 + hmin(t0,t1) +
// running hmin + set + LOP3 (stores 4-bit PAIR id) = 10 ops vs 12. Epilogue recomputes
// BOTH colors of the winning pair exactly in fp32 + fminf -> within-pair selection is
// exact, rel_err <= R9's 3e-5.
//  - MUFU-free packed Newton sqrt; single launch, wrap-around atomicInc reduction.

#define HW_       262144
#define CHW_      (3 * HW_)
#define THREADS_  128
#define BLOCKS_   2048
#define NTHR_     (THREADS_ * BLOCKS_)    // 262144 threads
#define INV_SIZE_ (1.0f / 6291456.0f)

typedef unsigned long long u64;
typedef unsigned int u32;

__device__ float g_partial[BLOCKS_];
__device__ u32   g_count = 0;

// ---- fp32x2 packed helpers ----
__device__ __forceinline__ u64 f2pk(float lo, float hi) {
    u64 r; asm("mov.b64 %0, {%1, %2};" : "=l"(r) : "f"(lo), "f"(hi)); return r;
}
__device__ __forceinline__ void f2unpk(u64 v, float& lo, float& hi) {
    asm("mov.b64 {%0, %1}, %2;" : "=f"(lo), "=f"(hi) : "l"(v));
}
__device__ __forceinline__ u64 fma2(u64 a, u64 b, u64 c) {
    u64 r; asm("fma.rn.f32x2 %0, %1, %2, %3;" : "=l"(r) : "l"(a), "l"(b), "l"(c)); return r;
}
__device__ __forceinline__ u64 mul2(u64 a, u64 b) {
    u64 r; asm("mul.rn.f32x2 %0, %1, %2;" : "=l"(r) : "l"(a), "l"(b)); return r;
}
__device__ __forceinline__ u64 add2(u64 a, u64 b) {
    u64 r; asm("add.rn.f32x2 %0, %1, %2;" : "=l"(r) : "l"(a), "l"(b)); return r;
}

// ---- fp16x2 on u32 helpers ----
__device__ __forceinline__ u32 hfma2u(u32 a, u32 b, u32 c) {
    u32 r; asm("fma.rn.f16x2 %0, %1, %2, %3;" : "=r"(r) : "r"(a), "r"(b), "r"(c)); return r;
}
__device__ __forceinline__ u32 hmin2u(u32 a, u32 b) {
    u32 r; asm("min.f16x2 %0, %1, %2;" : "=r"(r) : "r"(a), "r"(b)); return r;
}
// per-lane mask: 0xFFFF where a==b (as f16), else 0
__device__ __forceinline__ u32 heq2mask(u32 a, u32 b) {
    u32 r; asm("set.eq.u32.f16x2 %0, %1, %2;" : "=r"(r) : "r"(a), "r"(b)); return r;
}
// single-LOP3 masked select: (mk & kk) | (idx & ~mk)   [lut 0xCA]
__device__ __forceinline__ u32 sel3(u32 mk, u32 kk, u32 idx) {
    u32 r; asm("lop3.b32 %0, %1, %2, %3, 0xCA;" : "=r"(r) : "r"(mk), "r"(kk), "r"(idx));
    return r;
}
__device__ __forceinline__ u32 h2u(__half2 h) { return *reinterpret_cast<u32*>(&h); }

// MUFU-free packed sqrt: magic rsqrt seed + 2 Newton iters + x*r. x in [2e-6, ~13].
__device__ __forceinline__ u64 sqrt2_nomufu(u64 x, u64 C_H, u64 C_1p5) {
    float xl, xh;
    f2unpk(x, xl, xh);
    float rl = __int_as_float(0x5f3759df - (__float_as_int(xl) >> 1));
    float rh = __int_as_float(0x5f3759df - (__float_as_int(xh) >> 1));
    u64 r   = f2pk(rl, rh);
    u64 hxn = mul2(x, C_H);
    u64 m, u;
    m = mul2(r, r); u = fma2(hxn, m, C_1p5); r = mul2(r, u);
    m = mul2(r, r); u = fma2(hxn, m, C_1p5); r = mul2(r, u);
    return mul2(x, r);
}

__global__ __launch_bounds__(THREADS_, 8)
void nps_kernel(const float* __restrict__ adv,
                const float* __restrict__ prn,
                float* __restrict__ out)
{
    // fp16 weights per color: {W0h2, W1h2, W2h2, Ch2}, W=2*(1e-6-p) dup'd, C=sum v^2
    __shared__ uint4  shWC[30];
    // fp32 exact v per color: {v0, v1, v2, 0}
    __shared__ float4 shVC[30];
    __shared__ float  shRed[4];
    __shared__ int    shLast;

    int tid = threadIdx.x;
    if (tid < 30) {
        float v0 = 1e-6f - prn[tid * 3 + 0];
        float v1 = 1e-6f - prn[tid * 3 + 1];
        float v2 = 1e-6f - prn[tid * 3 + 2];
        float c  = v0 * v0 + v1 * v1 + v2 * v2;
        __half2 w0 = __float2half2_rn(2.f * v0);
        __half2 w1 = __float2half2_rn(2.f * v1);
        __half2 w2 = __float2half2_rn(2.f * v2);
        __half2 cc = __float2half2_rn(c);
        shWC[tid] = make_uint4(h2u(w0), h2u(w1), h2u(w2), h2u(cc));
        shVC[tid] = make_float4(v0, v1, v2, 0.f);
    }
    __syncthreads();

    // two float4-groups (8 pixels) per thread; fp32 kept live for the exact epilogue.
    int tglob = blockIdx.x * THREADS_ + tid;
    float4 a0, a1, a2, b0, b1, b2;
    {
        int p4 = tglob * 4;
        const float4* q = reinterpret_cast<const float4*>(
            adv + (size_t)(p4 >> 18) * CHW_ + (p4 & (HW_ - 1)));
        a0 = q[0]; a1 = q[HW_ / 4]; a2 = q[2 * (HW_ / 4)];
    }
    {
        int p4 = (tglob + NTHR_) * 4;
        const float4* q = reinterpret_cast<const float4*>(
            adv + (size_t)(p4 >> 18) * CHW_ + (p4 & (HW_ - 1)));
        b0 = q[0]; b1 = q[HW_ / 4]; b2 = q[2 * (HW_ / 4)];
    }

    // fp16 pixel pairs as u32: [pair][channel]
    u32 XA0 = h2u(__floats2half2_rn(a0.x, a0.y)), XA1 = h2u(__floats2half2_rn(a1.x, a1.y)),
        XA2 = h2u(__floats2half2_rn(a2.x, a2.y));
    u32 XB0 = h2u(__floats2half2_rn(a0.z, a0.w)), XB1 = h2u(__floats2half2_rn(a1.z, a1.w)),
        XB2 = h2u(__floats2half2_rn(a2.z, a2.w));
    u32 XC0 = h2u(__floats2half2_rn(b0.x, b0.y)), XC1 = h2u(__floats2half2_rn(b1.x, b1.y)),
        XC2 = h2u(__floats2half2_rn(b2.x, b2.y));
    u32 XD0 = h2u(__floats2half2_rn(b0.z, b0.w)), XD1 = h2u(__floats2half2_rn(b1.z, b1.w)),
        XD2 = h2u(__floats2half2_rn(b2.z, b2.w));

    u32 mA, mB, mC, mD;                            // running fp16 min over color-PAIRS
    u32 idxA = 0, idxB = 0, idxC = 0, idxD = 0;    // packed 16-bit PAIR id (0..14)

    {   // pair j = 0 peeled (colors 0,1)
        uint4 wa = shWC[0];
        uint4 wb = shWC[1];
        u32 t0, t1;
        t0 = hfma2u(wa.x, XA0, wa.w); t0 = hfma2u(wa.y, XA1, t0); t0 = hfma2u(wa.z, XA2, t0);
        t1 = hfma2u(wb.x, XA0, wb.w); t1 = hfma2u(wb.y, XA1, t1); t1 = hfma2u(wb.z, XA2, t1);
        mA = hmin2u(t0, t1);
        t0 = hfma2u(wa.x, XB0, wa.w); t0 = hfma2u(wa.y, XB1, t0); t0 = hfma2u(wa.z, XB2, t0);
        t1 = hfma2u(wb.x, XB0, wb.w); t1 = hfma2u(wb.y, XB1, t1); t1 = hfma2u(wb.z, XB2, t1);
        mB = hmin2u(t0, t1);
        t0 = hfma2u(wa.x, XC0, wa.w); t0 = hfma2u(wa.y, XC1, t0); t0 = hfma2u(wa.z, XC2, t0);
        t1 = hfma2u(wb.x, XC0, wb.w); t1 = hfma2u(wb.y, XC1, t1); t1 = hfma2u(wb.z, XC2, t1);
        mC = hmin2u(t0, t1);
        t0 = hfma2u(wa.x, XD0, wa.w); t0 = hfma2u(wa.y, XD1, t0); t0 = hfma2u(wa.z, XD2, t0);
        t1 = hfma2u(wb.x, XD0, wb.w); t1 = hfma2u(wb.y, XD1, t1); t1 = hfma2u(wb.z, XD2, t1);
        mD = hmin2u(t0, t1);
    }

    #pragma unroll
    for (int j = 1; j < 15; j++) {
        uint4 wa = shWC[2 * j];
        uint4 wb = shWC[2 * j + 1];
        u32 jj = (u32)j | ((u32)j << 16);
        u32 t0, t1, tp, mk;

        t0 = hfma2u(wa.x, XA0, wa.w); t0 = hfma2u(wa.y, XA1, t0); t0 = hfma2u(wa.z, XA2, t0);
        t1 = hfma2u(wb.x, XA0, wb.w); t1 = hfma2u(wb.y, XA1, t1); t1 = hfma2u(wb.z, XA2, t1);
        tp = hmin2u(t0, t1);
        mA = hmin2u(mA, tp); mk = heq2mask(tp, mA); idxA = sel3(mk, jj, idxA);

        t0 = hfma2u(wa.x, XB0, wa.w); t0 = hfma2u(wa.y, XB1, t0); t0 = hfma2u(wa.z, XB2, t0);
        t1 = hfma2u(wb.x, XB0, wb.w); t1 = hfma2u(wb.y, XB1, t1); t1 = hfma2u(wb.z, XB2, t1);
        tp = hmin2u(t0, t1);
        mB = hmin2u(mB, tp); mk = heq2mask(tp, mB); idxB = sel3(mk, jj, idxB);

        t0 = hfma2u(wa.x, XC0, wa.w); t0 = hfma2u(wa.y, XC1, t0); t0 = hfma2u(wa.z, XC2, t0);
        t1 = hfma2u(wb.x, XC0, wb.w); t1 = hfma2u(wb.y, XC1, t1); t1 = hfma2u(wb.z, XC2, t1);
        tp = hmin2u(t0, t1);
        mC = hmin2u(mC, tp); mk = heq2mask(tp, mC); idxC = sel3(mk, jj, idxC);

        t0 = hfma2u(wa.x, XD0, wa.w); t0 = hfma2u(wa.y, XD1, t0); t0 = hfma2u(wa.z, XD2, t0);
        t1 = hfma2u(wb.x, XD0, wb.w); t1 = hfma2u(wb.y, XD1, t1); t1 = hfma2u(wb.z, XD2, t1);
        tp = hmin2u(t0, t1);
        mD = hmin2u(mD, tp); mk = heq2mask(tp, mD); idxD = sel3(mk, jj, idxD);
    }

    // fp32 exact recompute: both colors of the winning pair, exact fminf between them.
    #define DIST2_(J, x0, x1, x2, OUTV)                                        \
    {                                                                          \
        int j_ = (int)(J);                                                     \
        float4 v_ = shVC[2 * j_];                                              \
        float e0 = x0 + v_.x, e1 = x1 + v_.y, e2 = x2 + v_.z;                  \
        float Da = fmaf(e0, e0, fmaf(e1, e1, fmaf(e2, e2, 1e-6f)));            \
        float4 u_ = shVC[2 * j_ + 1];                                          \
        float f0 = x0 + u_.x, f1 = x1 + u_.y, f2 = x2 + u_.z;                  \
        float Db = fmaf(f0, f0, fmaf(f1, f1, fmaf(f2, f2, 1e-6f)));            \
        OUTV = fminf(Da, Db);                                                  \
    }

    float D0, D1, D2, D3, D4, D5, D6, D7;
    DIST2_(idxA & 0xFFFF, a0.x, a1.x, a2.x, D0);
    DIST2_(idxA >> 16,    a0.y, a1.y, a2.y, D1);
    DIST2_(idxB & 0xFFFF, a0.z, a1.z, a2.z, D2);
    DIST2_(idxB >> 16,    a0.w, a1.w, a2.w, D3);
    DIST2_(idxC & 0xFFFF, b0.x, b1.x, b2.x, D4);
    DIST2_(idxC >> 16,    b0.y, b1.y, b2.y, D5);
    DIST2_(idxD & 0xFFFF, b0.z, b1.z, b2.z, D6);
    DIST2_(idxD >> 16,    b0.w, b1.w, b2.w, D7);
    #undef DIST2_

    const u64 C_H   = f2pk(-0.5f, -0.5f);
    const u64 C_1p5 = f2pk(1.5f, 1.5f);
    u64 qA = sqrt2_nomufu(f2pk(D0, D1), C_H, C_1p5);
    u64 qB = sqrt2_nomufu(f2pk(D2, D3), C_H, C_1p5);
    u64 qC = sqrt2_nomufu(f2pk(D4, D5), C_H, C_1p5);
    u64 qD = sqrt2_nomufu(f2pk(D6, D7), C_H, C_1p5);

    u64 ts = add2(add2(qA, qB), add2(qC, qD));
    float tl, th;
    f2unpk(ts, tl, th);
    float tsum = tl + th;

    // warp reduce
    #pragma unroll
    for (int off = 16; off > 0; off >>= 1)
        tsum += __shfl_xor_sync(0xffffffffu, tsum, off);
    if ((tid & 31) == 0) shRed[tid >> 5] = tsum;
    __syncthreads();

    if (tid == 0) {
        float bs = shRed[0] + shRed[1] + shRed[2] + shRed[3];
        g_partial[blockIdx.x] = bs;
        __threadfence();
        u32 prev = atomicInc(&g_count, BLOCKS_ - 1);
        shLast = (prev == BLOCKS_ - 1);
    }
    __syncthreads();

    if (shLast) {
        volatile float* vp = g_partial;
        float s = 0.0f;
        #pragma unroll
        for (int i = 0; i < BLOCKS_ / THREADS_; i++)
            s += vp[tid + i * THREADS_];
        #pragma unroll
        for (int off = 16; off > 0; off >>= 1)
            s += __shfl_xor_sync(0xffffffffu, s, off);
        if ((tid & 31) == 0) shRed[tid >> 5] = s;
        __syncthreads();
        if (tid == 0)
            out[0] = (shRed[0] + shRed[1] + shRed[2] + shRed[3]) * INV_SIZE_;
    }
}

extern "C" void kernel_launch(void* const* d_in, const int* in_sizes, int n_in,
                              void* d_out, int out_size)
{
    const float* adv = (const float*)d_in[0];   // (8,3,512,512) f32
    const float* prn = (const float*)d_in[1];   // (30,3) f32
    nps_kernel<<<BLOCKS_, THREADS_>>>(adv, prn, (float*)d_out);
}

// round 17
// speedup vs baseline: 1.0272x; 1.0272x over previous
#include <cuda_runtime.h>
#include <cuda_fp16.h>
#include <cuda_bf16.h>
#include <cstdint>

// NPSCalculator: nps = sum_{b,h,w} min_k sqrt( sum_c (x[b,c,h,w] - p[k,c] + 1e-6)^2 + 1e-6 ) / size
// B=8, C=3, H=512, W=512, NUM_COLORS=30.
//
// R17 = R14 (fp16 argmin + exact fp32 recompute, best passing 16.86us, rel_err 3e-5)
// with a shortened argmin dependency chain: the selection mask is computed against the
// OLD running min (set.le(t, m_old)) instead of the freshly-updated one, so set and hmin
// are independent and dual-issue; tie semantics identical (ties pick the newer k in both).
//  - hot loop per color per pixel-pair: 3 fma.f16x2 + {min.f16x2 || set.le} + LOP3.
//  - epilogue per pixel: exact fp32 recompute of winning color + MUFU-free Newton sqrt.
//  - single launch: per-block partials + wrap-around atomicInc last-block reduce.

#define HW_       262144
#define CHW_      (3 * HW_)
#define THREADS_  128
#define BLOCKS_   2048
#define NTHR_     (THREADS_ * BLOCKS_)    // 262144 threads
#define INV_SIZE_ (1.0f / 6291456.0f)

typedef unsigned long long u64;
typedef unsigned int u32;

__device__ float g_partial[BLOCKS_];
__device__ u32   g_count = 0;

// ---- fp32x2 packed helpers ----
__device__ __forceinline__ u64 f2pk(float lo, float hi) {
    u64 r; asm("mov.b64 %0, {%1, %2};" : "=l"(r) : "f"(lo), "f"(hi)); return r;
}
__device__ __forceinline__ void f2unpk(u64 v, float& lo, float& hi) {
    asm("mov.b64 {%0, %1}, %2;" : "=f"(lo), "=f"(hi) : "l"(v));
}
__device__ __forceinline__ u64 fma2(u64 a, u64 b, u64 c) {
    u64 r; asm("fma.rn.f32x2 %0, %1, %2, %3;" : "=l"(r) : "l"(a), "l"(b), "l"(c)); return r;
}
__device__ __forceinline__ u64 mul2(u64 a, u64 b) {
    u64 r; asm("mul.rn.f32x2 %0, %1, %2;" : "=l"(r) : "l"(a), "l"(b)); return r;
}
__device__ __forceinline__ u64 add2(u64 a, u64 b) {
    u64 r; asm("add.rn.f32x2 %0, %1, %2;" : "=l"(r) : "l"(a), "l"(b)); return r;
}

// ---- fp16x2 on u32 helpers ----
__device__ __forceinline__ u32 hfma2u(u32 a, u32 b, u32 c) {
    u32 r; asm("fma.rn.f16x2 %0, %1, %2, %3;" : "=r"(r) : "r"(a), "r"(b), "r"(c)); return r;
}
__device__ __forceinline__ u32 hmin2u(u32 a, u32 b) {
    u32 r; asm("min.f16x2 %0, %1, %2;" : "=r"(r) : "r"(a), "r"(b)); return r;
}
// per-lane mask: 0xFFFF where a<=b (as f16), else 0  -- compares against the OLD min
__device__ __forceinline__ u32 hle2mask(u32 a, u32 b) {
    u32 r; asm("set.le.u32.f16x2 %0, %1, %2;" : "=r"(r) : "r"(a), "r"(b)); return r;
}
// single-LOP3 masked select: (mk & kk) | (idx & ~mk)   [lut 0xCA]
__device__ __forceinline__ u32 sel3(u32 mk, u32 kk, u32 idx) {
    u32 r; asm("lop3.b32 %0, %1, %2, %3, 0xCA;" : "=r"(r) : "r"(mk), "r"(kk), "r"(idx));
    return r;
}
__device__ __forceinline__ u32 h2u(__half2 h) { return *reinterpret_cast<u32*>(&h); }

// MUFU-free packed sqrt: magic rsqrt seed + 2 Newton iters + x*r. x in [2e-6, ~13].
__device__ __forceinline__ u64 sqrt2_nomufu(u64 x, u64 C_H, u64 C_1p5) {
    float xl, xh;
    f2unpk(x, xl, xh);
    float rl = __int_as_float(0x5f3759df - (__float_as_int(xl) >> 1));
    float rh = __int_as_float(0x5f3759df - (__float_as_int(xh) >> 1));
    u64 r   = f2pk(rl, rh);
    u64 hxn = mul2(x, C_H);
    u64 m, u;
    m = mul2(r, r); u = fma2(hxn, m, C_1p5); r = mul2(r, u);
    m = mul2(r, r); u = fma2(hxn, m, C_1p5); r = mul2(r, u);
    return mul2(x, r);
}

__global__ __launch_bounds__(THREADS_, 7)
void nps_kernel(const float* __restrict__ adv,
                const float* __restrict__ prn,
                float* __restrict__ out)
{
    // fp16 weights per color: {W0h2, W1h2, W2h2, Ch2}, W=2*(1e-6-p) dup'd, C=sum v^2
    __shared__ uint4  shWC[30];
    // fp32 exact v per color: {v0, v1, v2, 0}
    __shared__ float4 shVC[30];
    __shared__ float  shRed[4];
    __shared__ int    shLast;

    int tid = threadIdx.x;
    if (tid < 30) {
        float v0 = 1e-6f - prn[tid * 3 + 0];
        float v1 = 1e-6f - prn[tid * 3 + 1];
        float v2 = 1e-6f - prn[tid * 3 + 2];
        float c  = v0 * v0 + v1 * v1 + v2 * v2;
        __half2 w0 = __float2half2_rn(2.f * v0);
        __half2 w1 = __float2half2_rn(2.f * v1);
        __half2 w2 = __float2half2_rn(2.f * v2);
        __half2 cc = __float2half2_rn(c);
        shWC[tid] = make_uint4(h2u(w0), h2u(w1), h2u(w2), h2u(cc));
        shVC[tid] = make_float4(v0, v1, v2, 0.f);
    }
    __syncthreads();

    // two float4-groups (8 pixels) per thread; fp32 kept live for the exact epilogue.
    int tglob = blockIdx.x * THREADS_ + tid;
    float4 a0, a1, a2, b0, b1, b2;
    {
        int p4 = tglob * 4;
        const float4* q = reinterpret_cast<const float4*>(
            adv + (size_t)(p4 >> 18) * CHW_ + (p4 & (HW_ - 1)));
        a0 = q[0]; a1 = q[HW_ / 4]; a2 = q[2 * (HW_ / 4)];
    }
    {
        int p4 = (tglob + NTHR_) * 4;
        const float4* q = reinterpret_cast<const float4*>(
            adv + (size_t)(p4 >> 18) * CHW_ + (p4 & (HW_ - 1)));
        b0 = q[0]; b1 = q[HW_ / 4]; b2 = q[2 * (HW_ / 4)];
    }

    // fp16 pixel pairs as u32: [pair][channel]
    u32 XA0 = h2u(__floats2half2_rn(a0.x, a0.y)), XA1 = h2u(__floats2half2_rn(a1.x, a1.y)),
        XA2 = h2u(__floats2half2_rn(a2.x, a2.y));
    u32 XB0 = h2u(__floats2half2_rn(a0.z, a0.w)), XB1 = h2u(__floats2half2_rn(a1.z, a1.w)),
        XB2 = h2u(__floats2half2_rn(a2.z, a2.w));
    u32 XC0 = h2u(__floats2half2_rn(b0.x, b0.y)), XC1 = h2u(__floats2half2_rn(b1.x, b1.y)),
        XC2 = h2u(__floats2half2_rn(b2.x, b2.y));
    u32 XD0 = h2u(__floats2half2_rn(b0.z, b0.w)), XD1 = h2u(__floats2half2_rn(b1.z, b1.w)),
        XD2 = h2u(__floats2half2_rn(b2.z, b2.w));

    u32 mA, mB, mC, mD;                            // running fp16 min of acc
    u32 idxA = 0, idxB = 0, idxC = 0, idxD = 0;    // packed 16-bit argmin

    // software-pipelined weight fetch: wnxt always loaded before the body consumes it
    uint4 w    = shWC[0];
    uint4 wnxt = shWC[1];
    {   // k = 0 peeled
        u32 t;
        t = hfma2u(w.x, XA0, w.w); t = hfma2u(w.y, XA1, t); mA = hfma2u(w.z, XA2, t);
        t = hfma2u(w.x, XB0, w.w); t = hfma2u(w.y, XB1, t); mB = hfma2u(w.z, XB2, t);
        t = hfma2u(w.x, XC0, w.w); t = hfma2u(w.y, XC1, t); mC = hfma2u(w.z, XC2, t);
        t = hfma2u(w.x, XD0, w.w); t = hfma2u(w.y, XD1, t); mD = hfma2u(w.z, XD2, t);
    }

    #pragma unroll
    for (int k = 1; k < 30; k++) {
        w = wnxt;
        if (k < 29) wnxt = shWC[k + 1];   // prefetch next color's weights (distance 1)

        u32 kk = (u32)k | ((u32)k << 16);
        u32 t, mk;

        // mask vs OLD min: set.le and hmin are independent -> dual-issue, chain depth 5
        t = hfma2u(w.x, XA0, w.w); t = hfma2u(w.y, XA1, t); t = hfma2u(w.z, XA2, t);
        mk = hle2mask(t, mA); mA = hmin2u(mA, t); idxA = sel3(mk, kk, idxA);

        t = hfma2u(w.x, XB0, w.w); t = hfma2u(w.y, XB1, t); t = hfma2u(w.z, XB2, t);
        mk = hle2mask(t, mB); mB = hmin2u(mB, t); idxB = sel3(mk, kk, idxB);

        t = hfma2u(w.x, XC0, w.w); t = hfma2u(w.y, XC1, t); t = hfma2u(w.z, XC2, t);
        mk = hle2mask(t, mC); mC = hmin2u(mC, t); idxC = sel3(mk, kk, idxC);

        t = hfma2u(w.x, XD0, w.w); t = hfma2u(w.y, XD1, t); t = hfma2u(w.z, XD2, t);
        mk = hle2mask(t, mD); mD = hmin2u(mD, t); idxD = sel3(mk, kk, idxD);
    }

    // fp32 exact recompute of the winning color's distance (matches reference bit-path)
    float D0, D1, D2, D3, D4, D5, D6, D7;
    {
        float4 v; float d0, d1, d2;
        v = shVC[idxA & 0xFFFF];
        d0 = a0.x + v.x; d1 = a1.x + v.y; d2 = a2.x + v.z;
        D0 = fmaf(d0, d0, fmaf(d1, d1, fmaf(d2, d2, 1e-6f)));
        v = shVC[idxA >> 16];
        d0 = a0.y + v.x; d1 = a1.y + v.y; d2 = a2.y + v.z;
        D1 = fmaf(d0, d0, fmaf(d1, d1, fmaf(d2, d2, 1e-6f)));
        v = shVC[idxB & 0xFFFF];
        d0 = a0.z + v.x; d1 = a1.z + v.y; d2 = a2.z + v.z;
        D2 = fmaf(d0, d0, fmaf(d1, d1, fmaf(d2, d2, 1e-6f)));
        v = shVC[idxB >> 16];
        d0 = a0.w + v.x; d1 = a1.w + v.y; d2 = a2.w + v.z;
        D3 = fmaf(d0, d0, fmaf(d1, d1, fmaf(d2, d2, 1e-6f)));
        v = shVC[idxC & 0xFFFF];
        d0 = b0.x + v.x; d1 = b1.x + v.y; d2 = b2.x + v.z;
        D4 = fmaf(d0, d0, fmaf(d1, d1, fmaf(d2, d2, 1e-6f)));
        v = shVC[idxC >> 16];
        d0 = b0.y + v.x; d1 = b1.y + v.y; d2 = b2.y + v.z;
        D5 = fmaf(d0, d0, fmaf(d1, d1, fmaf(d2, d2, 1e-6f)));
        v = shVC[idxD & 0xFFFF];
        d0 = b0.z + v.x; d1 = b1.z + v.y; d2 = b2.z + v.z;
        D6 = fmaf(d0, d0, fmaf(d1, d1, fmaf(d2, d2, 1e-6f)));
        v = shVC[idxD >> 16];
        d0 = b0.w + v.x; d1 = b1.w + v.y; d2 = b2.w + v.z;
        D7 = fmaf(d0, d0, fmaf(d1, d1, fmaf(d2, d2, 1e-6f)));
    }

    const u64 C_H   = f2pk(-0.5f, -0.5f);
    const u64 C_1p5 = f2pk(1.5f, 1.5f);
    u64 qA = sqrt2_nomufu(f2pk(D0, D1), C_H, C_1p5);
    u64 qB = sqrt2_nomufu(f2pk(D2, D3), C_H, C_1p5);
    u64 qC = sqrt2_nomufu(f2pk(D4, D5), C_H, C_1p5);
    u64 qD = sqrt2_nomufu(f2pk(D6, D7), C_H, C_1p5);

    u64 ts = add2(add2(qA, qB), add2(qC, qD));
    float tl, th;
    f2unpk(ts, tl, th);
    float tsum = tl + th;

    // warp reduce
    #pragma unroll
    for (int off = 16; off > 0; off >>= 1)
        tsum += __shfl_xor_sync(0xffffffffu, tsum, off);
    if ((tid & 31) == 0) shRed[tid >> 5] = tsum;
    __syncthreads();

    if (tid == 0) {
        float bs = shRed[0] + shRed[1] + shRed[2] + shRed[3];
        g_partial[blockIdx.x] = bs;
        __threadfence();
        u32 prev = atomicInc(&g_count, BLOCKS_ - 1);
        shLast = (prev == BLOCKS_ - 1);
    }
    __syncthreads();

    if (shLast) {
        volatile float* vp = g_partial;
        float s = 0.0f;
        #pragma unroll
        for (int i = 0; i < BLOCKS_ / THREADS_; i++)
            s += vp[tid + i * THREADS_];
        #pragma unroll
        for (int off = 16; off > 0; off >>= 1)
            s += __shfl_xor_sync(0xffffffffu, s, off);
        if ((tid & 31) == 0) shRed[tid >> 5] = s;
        __syncthreads();
        if (tid == 0)
            out[0] = (shRed[0] + shRed[1] + shRed[2] + shRed[3]) * INV_SIZE_;
    }
}

extern "C" void kernel_launch(void* const* d_in, const int* in_sizes, int n_in,
                              void* d_out, int out_size)
{
    const float* adv = (const float*)d_in[0];   // (8,3,512,512) f32
    const float* prn = (const float*)d_in[1];   // (30,3) f32
    nps_kernel<<<BLOCKS_, THREADS_>>>(adv, prn, (float*)d_out);
}